// round 4
// baseline (speedup 1.0000x reference)
#include <cuda_runtime.h>
#include <cstdint>

#define CIN   8
#define COUT  8
#define HH    1024
#define WW    1024
#define KK    31
#define PAD   15

#define TILE_X 64
#define TILE_Y 32
#define NTHREADS 256

// smem input tile: rows = TILE_Y + 30 = 62, cols padded to 96 (need 94)
#define SROWS 62
#define SCOLS 96
// weights for one ci: [co][i][j(32 padded)] as duplicated (w,w) 64-bit pairs
#define WSTRIDE (31 * 32)   // per-co elements

__device__ __forceinline__ unsigned long long f32x2_pack(float lo, float hi) {
    unsigned long long r;
    asm("mov.b64 %0, {%1, %2};" : "=l"(r) : "f"(lo), "f"(hi));
    return r;
}

__device__ __forceinline__ void f32x2_fma(unsigned long long& acc,
                                          unsigned long long a,
                                          unsigned long long b) {
    // acc = a * b + acc, elementwise on packed f32 pairs
    asm("fma.rn.f32x2 %0, %1, %2, %0;" : "+l"(acc) : "l"(a), "l"(b));
}

__device__ __forceinline__ void f32x2_unpack(unsigned long long v, float& lo, float& hi) {
    asm("mov.b64 {%0, %1}, %2;" : "=f"(lo), "=f"(hi) : "l"(v));
}

__global__ __launch_bounds__(NTHREADS, 2)
void fftconv_direct_kernel(const float* __restrict__ sig,
                           const float* __restrict__ wgt,
                           const float* __restrict__ bias,
                           float* __restrict__ out)
{
    __shared__ float s_in[SROWS * SCOLS];
    __shared__ unsigned long long s_w[COUT * WSTRIDE];

    const int t  = threadIdx.x;
    const int tx = t & 15;        // 16 threads across x, 4 cols each
    const int ty = t >> 4;        // 16 threads down y, 2 rows each
    const int x0 = blockIdx.x * TILE_X;
    const int y0 = blockIdx.y * TILE_Y;
    const int ci = blockIdx.z;    // one input channel per block

    // acc[co][q]: q=0 -> row0 cols(0,1), q=1 -> row0 cols(2,3),
    //             q=2 -> row1 cols(0,1), q=3 -> row1 cols(2,3)
    unsigned long long acc[COUT][4];
#pragma unroll
    for (int co = 0; co < COUT; ++co)
#pragma unroll
        for (int q = 0; q < 4; ++q)
            acc[co][q] = 0ULL;   // bit pattern 0 == (0.0f, 0.0f)

    // ---- stage input tile for this ci (zero-padded at borders) ----
    const float* sigc = sig + (size_t)ci * (HH * WW);
    for (int idx = t; idx < SROWS * SCOLS; idx += NTHREADS) {
        const int r  = idx / SCOLS;
        const int c  = idx - r * SCOLS;
        const int gr = y0 + r - PAD;
        const int gc = x0 + c - PAD;
        float v = 0.0f;
        if ((unsigned)gr < (unsigned)HH && (unsigned)gc < (unsigned)WW)
            v = sigc[gr * WW + gc];
        s_in[idx] = v;
    }
    // ---- stage weights for this ci, duplicated (w,w), j padded to 32 (col 31 = 0) ----
    for (int idx = t; idx < COUT * WSTRIDE; idx += NTHREADS) {
        const int co  = idx / WSTRIDE;
        const int rem = idx - co * WSTRIDE;
        const int i   = rem >> 5;       // /32
        const int j   = rem & 31;
        float v = 0.0f;
        if (j < KK)
            v = wgt[((co * CIN + ci) * KK + i) * KK + j];
        s_w[idx] = f32x2_pack(v, v);
    }
    __syncthreads();

    const int rowbase = 2 * ty;   // local output row (dy = 0)

#pragma unroll 1
    for (int i = 0; i < KK; ++i) {
        const float* r0 = s_in + (rowbase + i) * SCOLS + 4 * tx;
        const float* r1 = r0 + SCOLS;
        const unsigned long long* wbase = s_w + i * 32;

#pragma unroll
        for (int jc = 0; jc < 32; jc += 8) {
            // 12-float register windows per row (16B-aligned loads)
            float4 a0 = *(const float4*)(r0 + jc);
            float4 a1 = *(const float4*)(r0 + jc + 4);
            float4 a2 = *(const float4*)(r0 + jc + 8);
            float4 c0 = *(const float4*)(r1 + jc);
            float4 c1 = *(const float4*)(r1 + jc + 4);
            float4 c2 = *(const float4*)(r1 + jc + 8);
            float a[12], b[12];
            a[0]=a0.x; a[1]=a0.y; a[2]=a0.z; a[3]=a0.w;
            a[4]=a1.x; a[5]=a1.y; a[6]=a1.z; a[7]=a1.w;
            a[8]=a2.x; a[9]=a2.y; a[10]=a2.z; a[11]=a2.w;
            b[0]=c0.x; b[1]=c0.y; b[2]=c0.z; b[3]=c0.w;
            b[4]=c1.x; b[5]=c1.y; b[6]=c1.z; b[7]=c1.w;
            b[8]=c2.x; b[9]=c2.y; b[10]=c2.z; b[11]=c2.w;

            const unsigned long long* wj = wbase + jc;

#pragma unroll
            for (int j = 0; j < 8; ++j) {
                const unsigned long long p00 = f32x2_pack(a[j],     a[j + 1]);
                const unsigned long long p01 = f32x2_pack(a[j + 2], a[j + 3]);
                const unsigned long long p10 = f32x2_pack(b[j],     b[j + 1]);
                const unsigned long long p11 = f32x2_pack(b[j + 2], b[j + 3]);
#pragma unroll
                for (int co = 0; co < COUT; ++co) {
                    const unsigned long long w2 = wj[co * WSTRIDE + j];  // broadcast LDS.64
                    f32x2_fma(acc[co][0], p00, w2);
                    f32x2_fma(acc[co][1], p01, w2);
                    f32x2_fma(acc[co][2], p10, w2);
                    f32x2_fma(acc[co][3], p11, w2);
                }
            }
        }
    }

    // ---- epilogue: out[co][ci][y][x] = acc + bias[ci]  (bias indexes axis 1 = ci) ----
    const int gy = y0 + 2 * ty;
    const int gx = x0 + 4 * tx;
    const float bv = bias[ci];
#pragma unroll
    for (int co = 0; co < COUT; ++co) {
        float l0, h0, l1, h1;
        float* oplane = out + (((size_t)co * CIN + ci) * HH + gy) * WW + gx;

        f32x2_unpack(acc[co][0], l0, h0);
        f32x2_unpack(acc[co][1], l1, h1);
        *(float4*)oplane = make_float4(l0 + bv, h0 + bv, l1 + bv, h1 + bv);

        f32x2_unpack(acc[co][2], l0, h0);
        f32x2_unpack(acc[co][3], l1, h1);
        *(float4*)(oplane + WW) = make_float4(l0 + bv, h0 + bv, l1 + bv, h1 + bv);
    }
}

extern "C" void kernel_launch(void* const* d_in, const int* in_sizes, int n_in,
                              void* d_out, int out_size)
{
    const float* sig  = (const float*)d_in[0];   // [1, 8, 1024, 1024]
    const float* wgt  = (const float*)d_in[1];   // [8, 8, 31, 31]
    const float* bias = (const float*)d_in[2];   // [8]
    float* out = (float*)d_out;                  // [8, 8, 1024, 1024]  (co, ci, y, x)

    dim3 grid(WW / TILE_X, HH / TILE_Y, CIN);    // (16, 32, 8) = 4096 blocks
    fftconv_direct_kernel<<<grid, NTHREADS>>>(sig, wgt, bias, out);
}

// round 5
// speedup vs baseline: 1.7002x; 1.7002x over previous
#include <cuda_runtime.h>
#include <cstdint>

#define CIN   8
#define COUT  8
#define HH    1024
#define WW    1024
#define KK    31
#define PAD   15

#define TILE_X 64
#define TILE_Y 32
#define NTHREADS 256

// smem input tile: rows = TILE_Y + 30 = 62, cols padded to 100 (need 94).
// 100 mod 32 = 4 -> adjacent rows shift banks by 4, killing row conflicts.
#define SROWS 62
#define SCOLS 100

// weights for one ci, packed over co-pairs:
// s_w[(i*32 + j)*4 + cp] = (w[2cp][i][j], w[2cp+1][i][j]); j padded to 32 (j=31 -> 0)
#define NW (31 * 32 * 4)

__device__ __forceinline__ unsigned long long f32x2_dup(float v) {
    unsigned long long r;
    asm("mov.b64 %0, {%1, %1};" : "=l"(r) : "f"(v));
    return r;
}

__device__ __forceinline__ unsigned long long f32x2_pack(float lo, float hi) {
    unsigned long long r;
    asm("mov.b64 %0, {%1, %2};" : "=l"(r) : "f"(lo), "f"(hi));
    return r;
}

__device__ __forceinline__ void f32x2_fma(unsigned long long& acc,
                                          unsigned long long a,
                                          unsigned long long b) {
    asm("fma.rn.f32x2 %0, %1, %2, %0;" : "+l"(acc) : "l"(a), "l"(b));
}

__device__ __forceinline__ void f32x2_unpack(unsigned long long v, float& lo, float& hi) {
    asm("mov.b64 {%0, %1}, %2;" : "=f"(lo), "=f"(hi) : "l"(v));
}

__global__ __launch_bounds__(NTHREADS, 2)
void fftconv_direct_kernel(const float* __restrict__ sig,
                           const float* __restrict__ wgt,
                           const float* __restrict__ bias,
                           float* __restrict__ out)
{
    __shared__ float s_in[SROWS * SCOLS];
    __shared__ unsigned long long s_w[NW];

    const int t  = threadIdx.x;
    const int tx = t & 7;         // 8 threads across x, 8 cols each
    const int ty = t >> 3;        // 32 threads down y, 1 row each
    const int x0 = blockIdx.x * TILE_X;
    const int y0 = blockIdx.y * TILE_Y;
    const int ci = blockIdx.z;

    // acc[cp][p]: packed (out[2cp], out[2cp+1]) for pixel p of this thread's row
    unsigned long long acc[4][8];
#pragma unroll
    for (int cp = 0; cp < 4; ++cp)
#pragma unroll
        for (int p = 0; p < 8; ++p)
            acc[cp][p] = 0ULL;

    // ---- stage input tile for this ci (zero-padded at borders) ----
    const float* sigc = sig + (size_t)ci * (HH * WW);
    for (int idx = t; idx < SROWS * SCOLS; idx += NTHREADS) {
        const int r  = idx / SCOLS;
        const int c  = idx - r * SCOLS;
        const int gr = y0 + r - PAD;
        const int gc = x0 + c - PAD;
        float v = 0.0f;
        if ((unsigned)gr < (unsigned)HH && (unsigned)gc < (unsigned)WW)
            v = sigc[gr * WW + gc];
        s_in[idx] = v;
    }
    // ---- stage co-paired weights for this ci ----
    for (int idx = t; idx < NW; idx += NTHREADS) {
        const int i   = idx >> 7;        // /128 (32 j * 4 cp per i)
        const int rem = idx & 127;
        const int j   = rem >> 2;
        const int cp  = rem & 3;
        float w0 = 0.0f, w1 = 0.0f;
        if (j < KK) {
            const int co0 = 2 * cp;
            w0 = wgt[((co0 * CIN + ci) * KK + i) * KK + j];
            w1 = wgt[(((co0 + 1) * CIN + ci) * KK + i) * KK + j];
        }
        s_w[idx] = f32x2_pack(w0, w1);
    }
    __syncthreads();

#pragma unroll 1
    for (int i = 0; i < KK; ++i) {
        const float* rp = s_in + (ty + i) * SCOLS + 8 * tx;
        const unsigned long long* wrow = s_w + i * 128;   // 32 j * 4 cp

#pragma unroll
        for (int jc = 0; jc < 32; jc += 8) {
            // window cols 8tx+jc .. 8tx+jc+14 -> load 16, duplicate once each
            unsigned long long d[16];
            {
                float4 f0 = *(const float4*)(rp + jc);
                d[0] = f32x2_dup(f0.x); d[1] = f32x2_dup(f0.y);
                d[2] = f32x2_dup(f0.z); d[3] = f32x2_dup(f0.w);
                float4 f1 = *(const float4*)(rp + jc + 4);
                d[4] = f32x2_dup(f1.x); d[5] = f32x2_dup(f1.y);
                d[6] = f32x2_dup(f1.z); d[7] = f32x2_dup(f1.w);
                float4 f2 = *(const float4*)(rp + jc + 8);
                d[8]  = f32x2_dup(f2.x); d[9]  = f32x2_dup(f2.y);
                d[10] = f32x2_dup(f2.z); d[11] = f32x2_dup(f2.w);
                float4 f3 = *(const float4*)(rp + jc + 12);
                d[12] = f32x2_dup(f3.x); d[13] = f32x2_dup(f3.y);
                d[14] = f32x2_dup(f3.z); d[15] = f32x2_dup(f3.w);
            }

#pragma unroll
            for (int j = 0; j < 8; ++j) {
                // 2x LDS.128 broadcast: weights for 4 co-pairs at this (i, jc+j)
                const ulonglong2 w01 = *(const ulonglong2*)(wrow + (jc + j) * 4);
                const ulonglong2 w23 = *(const ulonglong2*)(wrow + (jc + j) * 4 + 2);
#pragma unroll
                for (int p = 0; p < 8; ++p) {
                    const unsigned long long dv = d[j + p];
                    f32x2_fma(acc[0][p], dv, w01.x);
                    f32x2_fma(acc[1][p], dv, w01.y);
                    f32x2_fma(acc[2][p], dv, w23.x);
                    f32x2_fma(acc[3][p], dv, w23.y);
                }
            }
        }
    }

    // ---- epilogue: out[co][ci][y][x] = acc + bias[ci] ----
    const int gy = y0 + ty;
    const int gx = x0 + 8 * tx;
    const float bv = bias[ci];
#pragma unroll
    for (int cp = 0; cp < 4; ++cp) {
        float lo[8], hi[8];
#pragma unroll
        for (int p = 0; p < 8; ++p)
            f32x2_unpack(acc[cp][p], lo[p], hi[p]);

        const int co0 = 2 * cp;
        float* o0 = out + (((size_t)co0       * CIN + ci) * HH + gy) * WW + gx;
        float* o1 = out + (((size_t)(co0 + 1) * CIN + ci) * HH + gy) * WW + gx;
        *(float4*)(o0)     = make_float4(lo[0] + bv, lo[1] + bv, lo[2] + bv, lo[3] + bv);
        *(float4*)(o0 + 4) = make_float4(lo[4] + bv, lo[5] + bv, lo[6] + bv, lo[7] + bv);
        *(float4*)(o1)     = make_float4(hi[0] + bv, hi[1] + bv, hi[2] + bv, hi[3] + bv);
        *(float4*)(o1 + 4) = make_float4(hi[4] + bv, hi[5] + bv, hi[6] + bv, hi[7] + bv);
    }
}

extern "C" void kernel_launch(void* const* d_in, const int* in_sizes, int n_in,
                              void* d_out, int out_size)
{
    const float* sig  = (const float*)d_in[0];   // [1, 8, 1024, 1024]
    const float* wgt  = (const float*)d_in[1];   // [8, 8, 31, 31]
    const float* bias = (const float*)d_in[2];   // [8]
    float* out = (float*)d_out;                  // [8, 8, 1024, 1024]  (co, ci, y, x)

    dim3 grid(WW / TILE_X, HH / TILE_Y, CIN);    // (16, 32, 8) = 4096 blocks
    fftconv_direct_kernel<<<grid, NTHREADS>>>(sig, wgt, bias, out);
}

// round 6
// speedup vs baseline: 1.7015x; 1.0008x over previous
#include <cuda_runtime.h>
#include <cstdint>

#define CIN   8
#define COUT  8
#define HH    1024
#define WW    1024
#define KK    31
#define PAD   15

#define TILE_X 64
#define TILE_Y 32
#define NTHREADS 256

// smem input tile: rows = TILE_Y + 30 = 62, cols padded to 100 (need 94).
// 100 mod 32 = 4 -> adjacent rows shift banks by 4, killing row conflicts.
#define SROWS 62
#define SCOLS 100

// weights for one ci, packed over co-pairs:
// s_w[(i*32 + j)*4 + cp] = (w[2cp][i][j], w[2cp+1][i][j]); j padded to 32 (j=31 -> 0)
#define NW (31 * 32 * 4)

__device__ __forceinline__ unsigned long long f32x2_dup(float v) {
    unsigned long long r;
    asm("mov.b64 %0, {%1, %1};" : "=l"(r) : "f"(v));
    return r;
}

__device__ __forceinline__ unsigned long long f32x2_pack(float lo, float hi) {
    unsigned long long r;
    asm("mov.b64 %0, {%1, %2};" : "=l"(r) : "f"(lo), "f"(hi));
    return r;
}

__device__ __forceinline__ void f32x2_fma(unsigned long long& acc,
                                          unsigned long long a,
                                          unsigned long long b) {
    asm("fma.rn.f32x2 %0, %1, %2, %0;" : "+l"(acc) : "l"(a), "l"(b));
}

__device__ __forceinline__ void f32x2_unpack(unsigned long long v, float& lo, float& hi) {
    asm("mov.b64 {%0, %1}, %2;" : "=f"(lo), "=f"(hi) : "l"(v));
}

__global__ __launch_bounds__(NTHREADS, 2)
void fftconv_direct_kernel(const float* __restrict__ sig,
                           const float* __restrict__ wgt,
                           const float* __restrict__ bias,
                           float* __restrict__ out)
{
    __shared__ float s_in[SROWS * SCOLS];
    __shared__ unsigned long long s_w[NW];

    const int t  = threadIdx.x;
    const int tx = t & 7;         // 8 threads across x, 8 cols each
    const int ty = t >> 3;        // 32 threads down y, 1 row each
    const int x0 = blockIdx.x * TILE_X;
    const int y0 = blockIdx.y * TILE_Y;
    const int ci = blockIdx.z;

    // acc[cp][p]: packed (out[2cp], out[2cp+1]) for pixel p of this thread's row
    unsigned long long acc[4][8];
#pragma unroll
    for (int cp = 0; cp < 4; ++cp)
#pragma unroll
        for (int p = 0; p < 8; ++p)
            acc[cp][p] = 0ULL;

    // ---- stage input tile for this ci (zero-padded at borders) ----
    const float* sigc = sig + (size_t)ci * (HH * WW);
    for (int idx = t; idx < SROWS * SCOLS; idx += NTHREADS) {
        const int r  = idx / SCOLS;
        const int c  = idx - r * SCOLS;
        const int gr = y0 + r - PAD;
        const int gc = x0 + c - PAD;
        float v = 0.0f;
        if ((unsigned)gr < (unsigned)HH && (unsigned)gc < (unsigned)WW)
            v = sigc[gr * WW + gc];
        s_in[idx] = v;
    }
    // ---- stage co-paired weights for this ci ----
    for (int idx = t; idx < NW; idx += NTHREADS) {
        const int i   = idx >> 7;        // /128 (32 j * 4 cp per i)
        const int rem = idx & 127;
        const int j   = rem >> 2;
        const int cp  = rem & 3;
        float w0 = 0.0f, w1 = 0.0f;
        if (j < KK) {
            const int co0 = 2 * cp;
            w0 = wgt[((co0 * CIN + ci) * KK + i) * KK + j];
            w1 = wgt[(((co0 + 1) * CIN + ci) * KK + i) * KK + j];
        }
        s_w[idx] = f32x2_pack(w0, w1);
    }
    __syncthreads();

#pragma unroll 1
    for (int i = 0; i < KK; ++i) {
        const float* rp = s_in + (ty + i) * SCOLS + 8 * tx;
        const unsigned long long* wrow = s_w + i * 128;   // 32 j * 4 cp

#pragma unroll
        for (int jc = 0; jc < 32; jc += 8) {
            // window cols 8tx+jc .. 8tx+jc+14 -> load 16, duplicate once each
            unsigned long long d[16];
            {
                float4 f0 = *(const float4*)(rp + jc);
                d[0] = f32x2_dup(f0.x); d[1] = f32x2_dup(f0.y);
                d[2] = f32x2_dup(f0.z); d[3] = f32x2_dup(f0.w);
                float4 f1 = *(const float4*)(rp + jc + 4);
                d[4] = f32x2_dup(f1.x); d[5] = f32x2_dup(f1.y);
                d[6] = f32x2_dup(f1.z); d[7] = f32x2_dup(f1.w);
                float4 f2 = *(const float4*)(rp + jc + 8);
                d[8]  = f32x2_dup(f2.x); d[9]  = f32x2_dup(f2.y);
                d[10] = f32x2_dup(f2.z); d[11] = f32x2_dup(f2.w);
                float4 f3 = *(const float4*)(rp + jc + 12);
                d[12] = f32x2_dup(f3.x); d[13] = f32x2_dup(f3.y);
                d[14] = f32x2_dup(f3.z); d[15] = f32x2_dup(f3.w);
            }

#pragma unroll
            for (int j = 0; j < 8; ++j) {
                // 2x LDS.128 broadcast: weights for 4 co-pairs at this (i, jc+j)
                const ulonglong2 w01 = *(const ulonglong2*)(wrow + (jc + j) * 4);
                const ulonglong2 w23 = *(const ulonglong2*)(wrow + (jc + j) * 4 + 2);
#pragma unroll
                for (int p = 0; p < 8; ++p) {
                    const unsigned long long dv = d[j + p];
                    f32x2_fma(acc[0][p], dv, w01.x);
                    f32x2_fma(acc[1][p], dv, w01.y);
                    f32x2_fma(acc[2][p], dv, w23.x);
                    f32x2_fma(acc[3][p], dv, w23.y);
                }
            }
        }
    }

    // ---- epilogue: out[co][ci][y][x] = acc + bias[ci] ----
    const int gy = y0 + ty;
    const int gx = x0 + 8 * tx;
    const float bv = bias[ci];
#pragma unroll
    for (int cp = 0; cp < 4; ++cp) {
        float lo[8], hi[8];
#pragma unroll
        for (int p = 0; p < 8; ++p)
            f32x2_unpack(acc[cp][p], lo[p], hi[p]);

        const int co0 = 2 * cp;
        float* o0 = out + (((size_t)co0       * CIN + ci) * HH + gy) * WW + gx;
        float* o1 = out + (((size_t)(co0 + 1) * CIN + ci) * HH + gy) * WW + gx;
        *(float4*)(o0)     = make_float4(lo[0] + bv, lo[1] + bv, lo[2] + bv, lo[3] + bv);
        *(float4*)(o0 + 4) = make_float4(lo[4] + bv, lo[5] + bv, lo[6] + bv, lo[7] + bv);
        *(float4*)(o1)     = make_float4(hi[0] + bv, hi[1] + bv, hi[2] + bv, hi[3] + bv);
        *(float4*)(o1 + 4) = make_float4(hi[4] + bv, hi[5] + bv, hi[6] + bv, hi[7] + bv);
    }
}

extern "C" void kernel_launch(void* const* d_in, const int* in_sizes, int n_in,
                              void* d_out, int out_size)
{
    const float* sig  = (const float*)d_in[0];   // [1, 8, 1024, 1024]
    const float* wgt  = (const float*)d_in[1];   // [8, 8, 31, 31]
    const float* bias = (const float*)d_in[2];   // [8]
    float* out = (float*)d_out;                  // [8, 8, 1024, 1024]  (co, ci, y, x)

    dim3 grid(WW / TILE_X, HH / TILE_Y, CIN);    // (16, 32, 8) = 4096 blocks
    fftconv_direct_kernel<<<grid, NTHREADS>>>(sig, wgt, bias, out);
}